// round 4
// baseline (speedup 1.0000x reference)
#include <cuda_runtime.h>
#include <math.h>

#define NB   128
#define NG   360
#define NGI  174
#define NEF  512
#define NET  512
#define NU   512
#define NAU  32
#define NVOC 5000
#define NT   20
#define NKX  (NEF + NET + NU)   // 1536
#define N4U  (4 * NU)           // 2048

// ---------------- scratch (device globals; no allocation allowed) ----------------
__device__ float g_feat[(size_t)NB * NG * NEF];   // [B,G,EF] post-LN encoder features
__device__ float g_f1[(size_t)NB * NG * NAU];     // hidden-independent attention half
__device__ float g_a[NB * NU];
__device__ float g_c[NB * NU];
__device__ float g_xfull[NB * NKX];               // [ctx | emb | a]
__device__ float g_gates[NB * N4U];
__device__ float g_Wcat[(size_t)N4U * NKX];       // [W_ih | W_hh] packed, row-major [N,K]
__device__ float g_bsum[N4U];
__device__ float g_d1[NB * 256];
__device__ float g_logits[(size_t)NB * NVOC];

// ---------------- helpers ----------------
__device__ __forceinline__ float warpSum(float v) {
    #pragma unroll
    for (int o = 16; o; o >>= 1) v += __shfl_xor_sync(0xffffffffu, v, o);
    return v;
}
__device__ __forceinline__ float warpMax(float v) {
    #pragma unroll
    for (int o = 16; o; o >>= 1) v = fmaxf(v, __shfl_xor_sync(0xffffffffu, v, o));
    return v;
}
__device__ __forceinline__ float blockSum(float v, float* sm) {
    __syncthreads();
    int lane = threadIdx.x & 31, wid = threadIdx.x >> 5;
    v = warpSum(v);
    if (lane == 0) sm[wid] = v;
    __syncthreads();
    int nw = blockDim.x >> 5;
    float r = (threadIdx.x < nw) ? sm[threadIdx.x] : 0.f;
    if (wid == 0) { r = warpSum(r); if (lane == 0) sm[0] = r; }
    __syncthreads();
    return sm[0];
}
__device__ __forceinline__ float blockMax(float v, float* sm) {
    __syncthreads();
    int lane = threadIdx.x & 31, wid = threadIdx.x >> 5;
    v = warpMax(v);
    if (lane == 0) sm[wid] = v;
    __syncthreads();
    int nw = blockDim.x >> 5;
    float r = (threadIdx.x < nw) ? sm[threadIdx.x] : -INFINITY;
    if (wid == 0) { r = warpMax(r); if (lane == 0) sm[0] = r; }
    __syncthreads();
    return sm[0];
}
__device__ __forceinline__ float sigmoidf(float x) { return 1.f / (1.f + expf(-x)); }
__device__ __forceinline__ float leakyf(float x)  { return x >= 0.f ? x : 0.2f * x; }

// ---------------- generic tiled SGEMM: C[M,N] = A[M,K] @ B + bias, epilogue ----------------
// BT=true : B stored [N,K] row-major (W_ih-style). BT=false : B stored [K,N].
// EPI: 0 none, 1 leaky, 2 relu.  Batched via grid.z with element strides.
template<bool BT, int EPI>
__global__ void __launch_bounds__(256) gemm_kernel(
    const float* __restrict__ A, int lda, size_t aBatch,
    const float* __restrict__ Bm, int ldb, size_t bBatch,
    const float* __restrict__ bias, size_t biasBatch,
    float* __restrict__ C, int ldc, size_t cBatch,
    int M, int N, int K)
{
    __shared__ float As[16][64];
    __shared__ float Bs[16][32];
    int z = blockIdx.z;
    A    += (size_t)z * aBatch;
    Bm   += (size_t)z * bBatch;
    bias += (size_t)z * biasBatch;
    C    += (size_t)z * cBatch;
    int n0 = blockIdx.x * 32;
    int m0 = blockIdx.y * 64;
    int tid = threadIdx.x;
    int tx = tid & 7;        // n quad: columns tx*4 .. tx*4+3
    int ty = tid >> 3;       // m pair: rows ty*2 .. ty*2+1
    int am = tid >> 2;       // A load row 0..63
    int ak = (tid & 3) << 2; // A load k base 0,4,8,12

    float acc[2][4] = {{0.f,0.f,0.f,0.f},{0.f,0.f,0.f,0.f}};
    int nchunks = (K + 15) >> 4;
    for (int kc = 0; kc < nchunks; kc++) {
        int k0 = kc << 4;
        // A tile (transposed into smem)
        #pragma unroll
        for (int j = 0; j < 4; j++) {
            int k = k0 + ak + j;
            As[ak + j][am] = (k < K) ? A[(size_t)(m0 + am) * lda + k] : 0.f;
        }
        // B tile
        if (BT) {
            int bk = tid & 15, nb = (tid >> 4) << 1;
            #pragma unroll
            for (int j = 0; j < 2; j++) {
                int n = nb + j, k = k0 + bk;
                float v = 0.f;
                if (n0 + n < N && k < K) v = Bm[(size_t)(n0 + n) * ldb + k];
                Bs[bk][n] = v;
            }
        } else {
            int bn = tid & 31, kb = (tid >> 5) << 1;
            #pragma unroll
            for (int j = 0; j < 2; j++) {
                int k = k0 + kb + j;
                float v = 0.f;
                if (n0 + bn < N && k < K) v = Bm[(size_t)k * ldb + n0 + bn];
                Bs[kb + j][bn] = v;
            }
        }
        __syncthreads();
        #pragma unroll
        for (int k = 0; k < 16; k++) {
            float2 a2 = *(const float2*)&As[k][ty * 2];
            float4 b4 = *(const float4*)&Bs[k][tx * 4];
            acc[0][0] += a2.x * b4.x; acc[0][1] += a2.x * b4.y;
            acc[0][2] += a2.x * b4.z; acc[0][3] += a2.x * b4.w;
            acc[1][0] += a2.y * b4.x; acc[1][1] += a2.y * b4.y;
            acc[1][2] += a2.y * b4.z; acc[1][3] += a2.y * b4.w;
        }
        __syncthreads();
    }
    #pragma unroll
    for (int i = 0; i < 2; i++) {
        int m = m0 + ty * 2 + i;
        #pragma unroll
        for (int j = 0; j < 4; j++) {
            int n = n0 + tx * 4 + j;
            if (n < N) {
                float v = acc[i][j] + bias[n];
                if (EPI == 1) v = leakyf(v);
                if (EPI == 2) v = fmaxf(v, 0.f);
                C[(size_t)m * ldc + n] = v;
            }
        }
    }
}

// ---------------- LayerNorm over rows of length 512 (in-place) ----------------
__global__ void __launch_bounds__(128) ln_rows_kernel(float* __restrict__ X,
    const float* __restrict__ gg, const float* __restrict__ bb)
{
    __shared__ float red[32];
    size_t row = blockIdx.x;
    float* xr = X + row * NEF;
    int tid = threadIdx.x;
    float v[4];
    #pragma unroll
    for (int j = 0; j < 4; j++) v[j] = xr[tid + 128 * j];
    float s = v[0] + v[1] + v[2] + v[3];
    float mean = blockSum(s, red) * (1.f / NEF);
    float sq = 0.f;
    #pragma unroll
    for (int j = 0; j < 4; j++) { float d = v[j] - mean; sq += d * d; }
    float var = blockSum(sq, red) * (1.f / NEF);
    float r = rsqrtf(var + 1e-5f);
    #pragma unroll
    for (int j = 0; j < 4; j++) {
        int cidx = tid + 128 * j;
        xr[cidx] = (v[j] - mean) * r * gg[cidx] + bb[cidx];
    }
}

// ---------------- pack [W_ih | W_hh] and b_ih + b_hh ----------------
__global__ void pack_kernel(const float* __restrict__ W_ih, const float* __restrict__ W_hh,
                            const float* __restrict__ b_ih, const float* __restrict__ b_hh)
{
    size_t idx = (size_t)blockIdx.x * blockDim.x + threadIdx.x;
    if (idx < (size_t)N4U * NKX) {
        int j = (int)(idx / NKX), k = (int)(idx % NKX);
        g_Wcat[idx] = (k < NEF + NET) ? W_ih[(size_t)j * (NEF + NET) + k]
                                      : W_hh[(size_t)j * NU + (k - NEF - NET)];
    }
    if (idx < N4U) g_bsum[idx] = b_ih[idx] + b_hh[idx];
}

__global__ void init_kernel(const float* __restrict__ a0, const float* __restrict__ c0)
{
    int idx = blockIdx.x * blockDim.x + threadIdx.x;
    if (idx < NB * NU) { g_a[idx] = a0[idx]; g_c[idx] = c0[idx]; }
}

// ---------------- attention step: h2, scores, softmax, ctx, xin pack ----------------
__global__ void __launch_bounds__(512) attn_kernel(
    const float* __restrict__ f1, const float* __restrict__ feat,
    const float* __restrict__ a,
    const float* __restrict__ W2, const float* __restrict__ b2,
    const float* __restrict__ V, const float* __restrict__ bV,
    const float* __restrict__ emb, const int* __restrict__ text,
    float* __restrict__ xfull, float* __restrict__ attn_out, int t)
{
    int b = blockIdx.x, tid = threadIdx.x;
    __shared__ float h2s[NAU];
    __shared__ float part[16][NAU];
    __shared__ float ss[NG];
    __shared__ float red[32];

    // h2 = relu(a @ W2 + b2), split K=512 across 16 segments
    {
        int au = tid & 31, seg = tid >> 5;
        const float* arow = a + b * NU;
        float acc = 0.f;
        #pragma unroll 8
        for (int kk = 0; kk < 32; kk++) {
            int k = seg * 32 + kk;
            acc += arow[k] * W2[k * NAU + au];
        }
        part[seg][au] = acc;
    }
    __syncthreads();
    if (tid < NAU) {
        float s = 0.f;
        #pragma unroll
        for (int i = 0; i < 16; i++) s += part[i][tid];
        h2s[tid] = fmaxf(s + b2[tid], 0.f);
    }
    __syncthreads();

    // scores: one warp per group
    int wid = tid >> 5, lane = tid & 31;
    for (int g = wid; g < NG; g += 16) {
        float v = tanhf(f1[((size_t)b * NG + g) * NAU + lane] + h2s[lane]) * V[lane];
        v = warpSum(v);
        if (lane == 0) ss[g] = v + bV[0];
    }
    __syncthreads();

    // softmax over G=360
    float mx = -INFINITY;
    for (int g = tid; g < NG; g += 512) mx = fmaxf(mx, ss[g]);
    mx = blockMax(mx, red);
    float sum = 0.f;
    for (int g = tid; g < NG; g += 512) { float e = expf(ss[g] - mx); ss[g] = e; sum += e; }
    sum = blockSum(sum, red);
    float inv = 1.f / sum;
    for (int g = tid; g < NG; g += 512) {
        float w = ss[g] * inv;
        ss[g] = w;
        if (attn_out) attn_out[((size_t)b * NT + t) * NG + g] = w;
    }
    __syncthreads();

    // ctx[ef] = sum_g w[g] * feat[b,g,ef]  (thread = one ef column)
    {
        float acc = 0.f;
        const float* fb = feat + (size_t)b * NG * NEF + tid;
        #pragma unroll 4
        for (int g = 0; g < NG; g++) acc += ss[g] * fb[(size_t)g * NEF];
        xfull[(size_t)b * NKX + tid] = acc;
    }
    // pack emb row and a row
    {
        int tok = text[b * NT + t];
        xfull[(size_t)b * NKX + NEF + tid] = emb[(size_t)tok * NET + tid];
        xfull[(size_t)b * NKX + NEF + NET + tid] = a[b * NU + tid];
    }
}

// ---------------- LSTM pointwise + LN(leaky(h)) ----------------
__global__ void __launch_bounds__(512) lstm_kernel(
    const float* __restrict__ gates, float* __restrict__ a, float* __restrict__ c,
    const float* __restrict__ lng, const float* __restrict__ lnb)
{
    __shared__ float red[32];
    int b = blockIdx.x, u = threadIdx.x;
    const float* gr = gates + (size_t)b * N4U;
    float gi = gr[u], gf = gr[NU + u], gg = gr[2 * NU + u], go = gr[3 * NU + u];
    float cn = sigmoidf(gf) * c[b * NU + u] + sigmoidf(gi) * tanhf(gg);
    float h  = sigmoidf(go) * tanhf(cn);
    c[b * NU + u] = cn;
    float hl = leakyf(h);
    float mean = blockSum(hl, red) * (1.f / NU);
    float d = hl - mean;
    float var = blockSum(d * d, red) * (1.f / NU);
    float r = rsqrtf(var + 1e-5f);
    a[b * NU + u] = d * r * lng[u] + lnb[u];
}

// ---------------- vocab softmax, writes output[b, t, :] ----------------
__global__ void __launch_bounds__(512) vsm_kernel(
    const float* __restrict__ logits, float* __restrict__ out, int t)
{
    __shared__ float red[32];
    int b = blockIdx.x, tid = threadIdx.x;
    const float* lr = logits + (size_t)b * NVOC;
    float* orow = out + ((size_t)b * NT + t) * NVOC;
    float mx = -INFINITY;
    for (int v = tid; v < NVOC; v += 512) mx = fmaxf(mx, lr[v]);
    mx = blockMax(mx, red);
    float s = 0.f;
    for (int v = tid; v < NVOC; v += 512) { float e = expf(lr[v] - mx); orow[v] = e; s += e; }
    s = blockSum(s, red);
    float inv = 1.f / s;
    for (int v = tid; v < NVOC; v += 512) orow[v] *= inv;
}

// ---------------- host ----------------
extern "C" void kernel_launch(void* const* d_in, const int* in_sizes, int n_in,
                              void* d_out, int out_size)
{
    const float* features = (const float*)d_in[0];
    const int*   text     = (const int*)  d_in[1];
    const float* a0       = (const float*)d_in[2];
    const float* c0       = (const float*)d_in[3];
    const float* enc_W    = (const float*)d_in[4];
    const float* enc_b    = (const float*)d_in[5];
    const float* enc_ln_g = (const float*)d_in[6];
    const float* enc_ln_b = (const float*)d_in[7];
    const float* attn_W1  = (const float*)d_in[8];
    const float* attn_b1  = (const float*)d_in[9];
    const float* attn_W2  = (const float*)d_in[10];
    const float* attn_b2  = (const float*)d_in[11];
    const float* attn_V   = (const float*)d_in[12];
    const float* attn_bV  = (const float*)d_in[13];
    const float* emb      = (const float*)d_in[14];
    const float* W_ih     = (const float*)d_in[15];
    const float* W_hh     = (const float*)d_in[16];
    const float* b_ih     = (const float*)d_in[17];
    const float* b_hh     = (const float*)d_in[18];
    const float* ln_g     = (const float*)d_in[19];
    const float* ln_b     = (const float*)d_in[20];
    const float* dec_W1   = (const float*)d_in[21];
    const float* dec_b1   = (const float*)d_in[22];
    const float* dec_W2   = (const float*)d_in[23];
    const float* dec_b2   = (const float*)d_in[24];

    float *p_feat, *p_f1, *p_a, *p_c, *p_x, *p_g, *p_W, *p_bs, *p_d1, *p_lg;
    cudaGetSymbolAddress((void**)&p_feat, g_feat);
    cudaGetSymbolAddress((void**)&p_f1,   g_f1);
    cudaGetSymbolAddress((void**)&p_a,    g_a);
    cudaGetSymbolAddress((void**)&p_c,    g_c);
    cudaGetSymbolAddress((void**)&p_x,    g_xfull);
    cudaGetSymbolAddress((void**)&p_g,    g_gates);
    cudaGetSymbolAddress((void**)&p_W,    g_Wcat);
    cudaGetSymbolAddress((void**)&p_bs,   g_bsum);
    cudaGetSymbolAddress((void**)&p_d1,   g_d1);
    cudaGetSymbolAddress((void**)&p_lg,   g_logits);

    float* out = (float*)d_out;
    float* attn_out = nullptr;
    long long need = (long long)NB * NT * NVOC + (long long)NB * NT * NG;
    if ((long long)out_size >= need) attn_out = out + (size_t)NB * NT * NVOC;

    pack_kernel<<<(int)(((size_t)N4U * NKX + 255) / 256), 256>>>(W_ih, W_hh, b_ih, b_hh);
    init_kernel<<<(NB * NU + 255) / 256, 256>>>(a0, c0);

    // encoder: per-group GEMM [128 x 174 x 512] + leaky, then LN
    {
        dim3 ge(NEF / 32, NB / 64, NG);
        gemm_kernel<false, 1><<<ge, 256>>>(
            features, NG * NGI, (size_t)NGI,
            enc_W, NEF, (size_t)NGI * NEF,
            enc_b, (size_t)NEF,
            p_feat, NG * NEF, (size_t)NEF,
            NB, NEF, NGI);
        ln_rows_kernel<<<NB * NG, 128>>>(p_feat, enc_ln_g, enc_ln_b);
    }
    // f1 = relu(feat @ attn_W1 + b1): [46080 x 512 x 32]
    {
        dim3 gf1(1, (NB * NG) / 64, 1);
        gemm_kernel<false, 2><<<gf1, 256>>>(
            p_feat, NEF, 0, attn_W1, NAU, 0, attn_b1, 0,
            p_f1, NAU, 0, NB * NG, NAU, NEF);
    }

    for (int t = 0; t < NT; t++) {
        attn_kernel<<<NB, 512>>>(p_f1, p_feat, p_a, attn_W2, attn_b2, attn_V, attn_bV,
                                 emb, text, p_x, attn_out, t);
        {   // gates = xin @ Wcat^T + bsum : [128 x 1536 x 2048]
            dim3 gg(N4U / 32, NB / 64, 1);
            gemm_kernel<true, 0><<<gg, 256>>>(
                p_x, NKX, 0, p_W, NKX, 0, p_bs, 0,
                p_g, N4U, 0, NB, N4U, NKX);
        }
        lstm_kernel<<<NB, 512>>>(p_g, p_a, p_c, ln_g, ln_b);
        {   // d1 = leaky(a @ dec_W1 + b1): [128 x 512 x 256]
            dim3 gd1(256 / 32, NB / 64, 1);
            gemm_kernel<false, 1><<<gd1, 256>>>(
                p_a, NU, 0, dec_W1, 256, 0, dec_b1, 0,
                p_d1, 256, 0, NB, 256, NU);
        }
        {   // logits = d1 @ dec_W2 + b2: [128 x 256 x 5000]
            dim3 gd2((NVOC + 31) / 32, NB / 64, 1);
            gemm_kernel<false, 0><<<gd2, 256>>>(
                p_d1, 256, 0, dec_W2, NVOC, 0, dec_b2, 0,
                p_lg, NVOC, 0, NB, NVOC, 256);
        }
        vsm_kernel<<<NB, 512>>>(p_lg, out, t);
    }
}

// round 5
// speedup vs baseline: 2.0291x; 2.0291x over previous
#include <cuda_runtime.h>
#include <math.h>

#define NB   128
#define NG   360
#define NGI  174
#define NEF  512
#define NET  512
#define NU   512
#define NAU  32
#define NVOC 5000
#define NT   20
#define NKX  (NEF + NET + NU)   // 1536
#define N4U  (4 * NU)           // 2048
#define NSK  4                  // split-K factor for gates GEMM
#define NKSP (NKX / NSK)        // 384

// ---------------- scratch (device globals; no allocation allowed) ----------------
__device__ float g_feat[(size_t)NB * NG * NEF];        // [B,G,EF] post-LN encoder features
__device__ float g_f1[(size_t)NB * NG * NAU];          // hidden-independent attention half
__device__ float g_aseq[(size_t)(NT + 1) * NB * NU];   // a_t sequence; slot 0 = a0
__device__ float g_c[NB * NU];
__device__ float g_xfull[NB * NKX];                    // [ctx | emb | a]
__device__ float g_gpart[(size_t)NSK * NB * N4U];      // split-K partials
__device__ float g_Wcat[(size_t)N4U * NKX];            // [W_ih | W_hh] packed [N,K]
__device__ float g_bsum[N4U];
__device__ float g_d1big[(size_t)NT * NB * 256];
__device__ float g_lgbig[(size_t)NT * NB * NVOC];

// ---------------- helpers ----------------
__device__ __forceinline__ float warpSum(float v) {
    #pragma unroll
    for (int o = 16; o; o >>= 1) v += __shfl_xor_sync(0xffffffffu, v, o);
    return v;
}
__device__ __forceinline__ float warpMax(float v) {
    #pragma unroll
    for (int o = 16; o; o >>= 1) v = fmaxf(v, __shfl_xor_sync(0xffffffffu, v, o));
    return v;
}
__device__ __forceinline__ float blockSum(float v, float* sm) {
    __syncthreads();
    int lane = threadIdx.x & 31, wid = threadIdx.x >> 5;
    v = warpSum(v);
    if (lane == 0) sm[wid] = v;
    __syncthreads();
    int nw = blockDim.x >> 5;
    float r = (threadIdx.x < nw) ? sm[threadIdx.x] : 0.f;
    if (wid == 0) { r = warpSum(r); if (lane == 0) sm[0] = r; }
    __syncthreads();
    return sm[0];
}
__device__ __forceinline__ float blockMax(float v, float* sm) {
    __syncthreads();
    int lane = threadIdx.x & 31, wid = threadIdx.x >> 5;
    v = warpMax(v);
    if (lane == 0) sm[wid] = v;
    __syncthreads();
    int nw = blockDim.x >> 5;
    float r = (threadIdx.x < nw) ? sm[threadIdx.x] : -INFINITY;
    if (wid == 0) { r = warpMax(r); if (lane == 0) sm[0] = r; }
    __syncthreads();
    return sm[0];
}
__device__ __forceinline__ float sigmoidf(float x) { return 1.f / (1.f + expf(-x)); }
__device__ __forceinline__ float leakyf(float x)  { return x >= 0.f ? x : 0.2f * x; }

// ---------------- 64x64-tile SGEMM, 4x4 microtile, double-buffered ----------------
// C[M,N] = A[M,K] @ B (+ bias), EPI: 0 none, 1 leaky, 2 relu.
// BT=true : B stored [N,K] row-major. BT=false : B stored [K,N].
// Batched via grid.z with element-offset strides (aBatch applied as flat offset).
template<bool BT, int EPI>
__global__ void __launch_bounds__(256) gemm64_kernel(
    const float* __restrict__ A, int lda, size_t aBatch,
    const float* __restrict__ Bm, int ldb, size_t bBatch,
    const float* __restrict__ bias, size_t biasBatch,
    float* __restrict__ C, int ldc, size_t cBatch,
    int M, int N, int K)
{
    __shared__ __align__(16) float As[2][16][68];
    __shared__ __align__(16) float Bs[2][16][68];
    A    += (size_t)blockIdx.z * aBatch;
    Bm   += (size_t)blockIdx.z * bBatch;
    if (bias) bias += (size_t)blockIdx.z * biasBatch;
    C    += (size_t)blockIdx.z * cBatch;

    const int n0 = blockIdx.x * 64;
    const int m0 = blockIdx.y * 64;
    const int tid = threadIdx.x;
    const int tx = tid & 15;          // n microtile: cols tx*4..tx*4+3
    const int ty = tid >> 4;          // m microtile: rows ty*4..ty*4+3
    // A staging: row am (0..63), k base ak (0,4,8,12)
    const int am = tid >> 2;
    const int ak = (tid & 3) << 2;
    // B staging (BT=false): k row bkf (0..15), n base bnf
    const int bkf = tid >> 4;
    const int bnf = (tid & 15) << 2;
    // B staging (BT=true): n row bnr (0..63), k base bkr
    const int bnr = tid >> 2;
    const int bkr = (tid & 3) << 2;

    float acc[4][4] = {};
    float aR[4], bR[4];
    const int nch = (K + 15) >> 4;
    const bool mok = (m0 + am) < M;

    // prologue: global-load chunk 0
    #pragma unroll
    for (int j = 0; j < 4; j++) {
        int k = ak + j;
        aR[j] = (mok && k < K) ? A[(size_t)(m0 + am) * lda + k] : 0.f;
    }
    if (BT) {
        #pragma unroll
        for (int j = 0; j < 4; j++) {
            int k = bkr + j;
            bR[j] = ((n0 + bnr) < N && k < K) ? Bm[(size_t)(n0 + bnr) * ldb + k] : 0.f;
        }
    } else {
        #pragma unroll
        for (int j = 0; j < 4; j++) {
            int n = n0 + bnf + j;
            bR[j] = (n < N && bkf < K) ? Bm[(size_t)bkf * ldb + n] : 0.f;
        }
    }
    #pragma unroll
    for (int j = 0; j < 4; j++) As[0][ak + j][am] = aR[j];
    if (BT) {
        #pragma unroll
        for (int j = 0; j < 4; j++) Bs[0][bkr + j][bnr] = bR[j];
    } else {
        #pragma unroll
        for (int j = 0; j < 4; j++) Bs[0][bkf][bnf + j] = bR[j];
    }
    __syncthreads();

    for (int kc = 0; kc < nch; kc++) {
        const int cur = kc & 1, nxt = cur ^ 1;
        const bool more = (kc + 1) < nch;
        if (more) {
            const int k0 = (kc + 1) << 4;
            #pragma unroll
            for (int j = 0; j < 4; j++) {
                int k = k0 + ak + j;
                aR[j] = (mok && k < K) ? A[(size_t)(m0 + am) * lda + k] : 0.f;
            }
            if (BT) {
                #pragma unroll
                for (int j = 0; j < 4; j++) {
                    int k = k0 + bkr + j;
                    bR[j] = ((n0 + bnr) < N && k < K) ? Bm[(size_t)(n0 + bnr) * ldb + k] : 0.f;
                }
            } else {
                #pragma unroll
                for (int j = 0; j < 4; j++) {
                    int n = n0 + bnf + j;
                    int k = k0 + bkf;
                    bR[j] = (n < N && k < K) ? Bm[(size_t)k * ldb + n] : 0.f;
                }
            }
        }
        #pragma unroll
        for (int k = 0; k < 16; k++) {
            float4 a4 = *(const float4*)&As[cur][k][ty << 2];
            float4 b4 = *(const float4*)&Bs[cur][k][tx << 2];
            acc[0][0] += a4.x * b4.x; acc[0][1] += a4.x * b4.y;
            acc[0][2] += a4.x * b4.z; acc[0][3] += a4.x * b4.w;
            acc[1][0] += a4.y * b4.x; acc[1][1] += a4.y * b4.y;
            acc[1][2] += a4.y * b4.z; acc[1][3] += a4.y * b4.w;
            acc[2][0] += a4.z * b4.x; acc[2][1] += a4.z * b4.y;
            acc[2][2] += a4.z * b4.z; acc[2][3] += a4.z * b4.w;
            acc[3][0] += a4.w * b4.x; acc[3][1] += a4.w * b4.y;
            acc[3][2] += a4.w * b4.z; acc[3][3] += a4.w * b4.w;
        }
        if (more) {
            #pragma unroll
            for (int j = 0; j < 4; j++) As[nxt][ak + j][am] = aR[j];
            if (BT) {
                #pragma unroll
                for (int j = 0; j < 4; j++) Bs[nxt][bkr + j][bnr] = bR[j];
            } else {
                #pragma unroll
                for (int j = 0; j < 4; j++) Bs[nxt][bkf][bnf + j] = bR[j];
            }
            __syncthreads();
        }
    }

    #pragma unroll
    for (int i = 0; i < 4; i++) {
        int m = m0 + (ty << 2) + i;
        if (m < M) {
            #pragma unroll
            for (int j = 0; j < 4; j++) {
                int n = n0 + (tx << 2) + j;
                if (n < N) {
                    float v = acc[i][j] + (bias ? bias[n] : 0.f);
                    if (EPI == 1) v = leakyf(v);
                    if (EPI == 2) v = fmaxf(v, 0.f);
                    C[(size_t)m * ldc + n] = v;
                }
            }
        }
    }
}

// ---------------- LayerNorm over rows of length 512 (in-place) ----------------
__global__ void __launch_bounds__(128) ln_rows_kernel(float* __restrict__ X,
    const float* __restrict__ gg, const float* __restrict__ bb)
{
    __shared__ float red[32];
    size_t row = blockIdx.x;
    float* xr = X + row * NEF;
    int tid = threadIdx.x;
    float v[4];
    #pragma unroll
    for (int j = 0; j < 4; j++) v[j] = xr[tid + 128 * j];
    float s = v[0] + v[1] + v[2] + v[3];
    float mean = blockSum(s, red) * (1.f / NEF);
    float sq = 0.f;
    #pragma unroll
    for (int j = 0; j < 4; j++) { float d = v[j] - mean; sq += d * d; }
    float var = blockSum(sq, red) * (1.f / NEF);
    float r = rsqrtf(var + 1e-5f);
    #pragma unroll
    for (int j = 0; j < 4; j++) {
        int cidx = tid + 128 * j;
        xr[cidx] = (v[j] - mean) * r * gg[cidx] + bb[cidx];
    }
}

// ---------------- pack [W_ih | W_hh] and b_ih + b_hh ----------------
__global__ void pack_kernel(const float* __restrict__ W_ih, const float* __restrict__ W_hh,
                            const float* __restrict__ b_ih, const float* __restrict__ b_hh)
{
    size_t idx = (size_t)blockIdx.x * blockDim.x + threadIdx.x;
    if (idx < (size_t)N4U * NKX) {
        int j = (int)(idx / NKX), k = (int)(idx % NKX);
        g_Wcat[idx] = (k < NEF + NET) ? W_ih[(size_t)j * (NEF + NET) + k]
                                      : W_hh[(size_t)j * NU + (k - NEF - NET)];
    }
    if (idx < N4U) g_bsum[idx] = b_ih[idx] + b_hh[idx];
}

__global__ void init_kernel(const float* __restrict__ a0, const float* __restrict__ c0)
{
    int idx = blockIdx.x * blockDim.x + threadIdx.x;
    if (idx < NB * NU) { g_aseq[idx] = a0[idx]; g_c[idx] = c0[idx]; }
}

// ---------------- attention step: h2, scores, softmax, ctx, xin pack ----------------
__global__ void __launch_bounds__(512) attn_kernel(
    const float* __restrict__ f1, const float* __restrict__ feat,
    const float* __restrict__ a,
    const float* __restrict__ W2, const float* __restrict__ b2,
    const float* __restrict__ V, const float* __restrict__ bV,
    const float* __restrict__ emb, const int* __restrict__ text,
    float* __restrict__ xfull, float* __restrict__ attn_out, int t)
{
    int b = blockIdx.x, tid = threadIdx.x;
    __shared__ float h2s[NAU];
    __shared__ float part[16][NAU];
    __shared__ float ss[NG];
    __shared__ float red[32];

    // h2 = relu(a @ W2 + b2), split K=512 across 16 segments
    {
        int au = tid & 31, seg = tid >> 5;
        const float* arow = a + b * NU;
        float acc = 0.f;
        #pragma unroll 8
        for (int kk = 0; kk < 32; kk++) {
            int k = seg * 32 + kk;
            acc += arow[k] * W2[k * NAU + au];
        }
        part[seg][au] = acc;
    }
    __syncthreads();
    if (tid < NAU) {
        float s = 0.f;
        #pragma unroll
        for (int i = 0; i < 16; i++) s += part[i][tid];
        h2s[tid] = fmaxf(s + b2[tid], 0.f);
    }
    __syncthreads();

    // scores: one warp per group
    int wid = tid >> 5, lane = tid & 31;
    for (int g = wid; g < NG; g += 16) {
        float v = tanhf(f1[((size_t)b * NG + g) * NAU + lane] + h2s[lane]) * V[lane];
        v = warpSum(v);
        if (lane == 0) ss[g] = v + bV[0];
    }
    __syncthreads();

    // softmax over G=360
    float mx = -INFINITY;
    for (int g = tid; g < NG; g += 512) mx = fmaxf(mx, ss[g]);
    mx = blockMax(mx, red);
    float sum = 0.f;
    for (int g = tid; g < NG; g += 512) { float e = expf(ss[g] - mx); ss[g] = e; sum += e; }
    sum = blockSum(sum, red);
    float inv = 1.f / sum;
    for (int g = tid; g < NG; g += 512) {
        float w = ss[g] * inv;
        ss[g] = w;
        if (attn_out) attn_out[((size_t)b * NT + t) * NG + g] = w;
    }
    __syncthreads();

    // ctx[ef] = sum_g w[g] * feat[b,g,ef]  (thread = one ef column)
    {
        float acc = 0.f;
        const float* fb = feat + (size_t)b * NG * NEF + tid;
        #pragma unroll 4
        for (int g = 0; g < NG; g++) acc += ss[g] * fb[(size_t)g * NEF];
        xfull[(size_t)b * NKX + tid] = acc;
    }
    // pack emb row and a row
    {
        int tok = text[b * NT + t];
        xfull[(size_t)b * NKX + NEF + tid] = emb[(size_t)tok * NET + tid];
        xfull[(size_t)b * NKX + NEF + NET + tid] = a[b * NU + tid];
    }
}

// ---------------- LSTM: reduce split-K partials + pointwise + LN(leaky(h)) ----------------
__global__ void __launch_bounds__(512) lstm_kernel(
    const float* __restrict__ gpart, float* __restrict__ aout, float* __restrict__ c,
    const float* __restrict__ lng, const float* __restrict__ lnb,
    const float* __restrict__ bsum)
{
    __shared__ float red[32];
    int b = blockIdx.x, u = threadIdx.x;
    float gi = bsum[u], gf = bsum[NU + u], gg = bsum[2 * NU + u], go = bsum[3 * NU + u];
    #pragma unroll
    for (int z = 0; z < NSK; z++) {
        const float* gr = gpart + (size_t)z * NB * N4U + (size_t)b * N4U;
        gi += gr[u]; gf += gr[NU + u]; gg += gr[2 * NU + u]; go += gr[3 * NU + u];
    }
    float cn = sigmoidf(gf) * c[b * NU + u] + sigmoidf(gi) * tanhf(gg);
    float h  = sigmoidf(go) * tanhf(cn);
    c[b * NU + u] = cn;
    float hl = leakyf(h);
    float mean = blockSum(hl, red) * (1.f / NU);
    float d = hl - mean;
    float var = blockSum(d * d, red) * (1.f / NU);
    float r = rsqrtf(var + 1e-5f);
    aout[b * NU + u] = d * r * lng[u] + lnb[u];
}

// ---------------- batched vocab softmax: rows r = t*NB + b -> out[b,t,:] ----------------
__global__ void __launch_bounds__(512) vsm_kernel(
    const float* __restrict__ logits, float* __restrict__ out)
{
    __shared__ float red[32];
    int r = blockIdx.x, tid = threadIdx.x;
    int t = r / NB, b = r % NB;
    const float* lr = logits + (size_t)r * NVOC;
    float* orow = out + ((size_t)b * NT + t) * NVOC;
    float mx = -INFINITY;
    for (int v = tid; v < NVOC; v += 512) mx = fmaxf(mx, lr[v]);
    mx = blockMax(mx, red);
    float s = 0.f;
    for (int v = tid; v < NVOC; v += 512) { float e = expf(lr[v] - mx); orow[v] = e; s += e; }
    s = blockSum(s, red);
    float inv = 1.f / s;
    for (int v = tid; v < NVOC; v += 512) orow[v] *= inv;
}

// ---------------- host ----------------
extern "C" void kernel_launch(void* const* d_in, const int* in_sizes, int n_in,
                              void* d_out, int out_size)
{
    const float* features = (const float*)d_in[0];
    const int*   text     = (const int*)  d_in[1];
    const float* a0       = (const float*)d_in[2];
    const float* c0       = (const float*)d_in[3];
    const float* enc_W    = (const float*)d_in[4];
    const float* enc_b    = (const float*)d_in[5];
    const float* enc_ln_g = (const float*)d_in[6];
    const float* enc_ln_b = (const float*)d_in[7];
    const float* attn_W1  = (const float*)d_in[8];
    const float* attn_b1  = (const float*)d_in[9];
    const float* attn_W2  = (const float*)d_in[10];
    const float* attn_b2  = (const float*)d_in[11];
    const float* attn_V   = (const float*)d_in[12];
    const float* attn_bV  = (const float*)d_in[13];
    const float* emb      = (const float*)d_in[14];
    const float* W_ih     = (const float*)d_in[15];
    const float* W_hh     = (const float*)d_in[16];
    const float* b_ih     = (const float*)d_in[17];
    const float* b_hh     = (const float*)d_in[18];
    const float* ln_g     = (const float*)d_in[19];
    const float* ln_b     = (const float*)d_in[20];
    const float* dec_W1   = (const float*)d_in[21];
    const float* dec_b1   = (const float*)d_in[22];
    const float* dec_W2   = (const float*)d_in[23];
    const float* dec_b2   = (const float*)d_in[24];

    float *p_feat, *p_f1, *p_aseq, *p_c, *p_x, *p_gp, *p_W, *p_bs, *p_d1, *p_lg;
    cudaGetSymbolAddress((void**)&p_feat, g_feat);
    cudaGetSymbolAddress((void**)&p_f1,   g_f1);
    cudaGetSymbolAddress((void**)&p_aseq, g_aseq);
    cudaGetSymbolAddress((void**)&p_c,    g_c);
    cudaGetSymbolAddress((void**)&p_x,    g_xfull);
    cudaGetSymbolAddress((void**)&p_gp,   g_gpart);
    cudaGetSymbolAddress((void**)&p_W,    g_Wcat);
    cudaGetSymbolAddress((void**)&p_bs,   g_bsum);
    cudaGetSymbolAddress((void**)&p_d1,   g_d1big);
    cudaGetSymbolAddress((void**)&p_lg,   g_lgbig);

    float* out = (float*)d_out;
    float* attn_out = nullptr;
    long long need = (long long)NB * NT * NVOC + (long long)NB * NT * NG;
    if ((long long)out_size >= need) attn_out = out + (size_t)NB * NT * NVOC;

    pack_kernel<<<(int)(((size_t)N4U * NKX + 255) / 256), 256>>>(W_ih, W_hh, b_ih, b_hh);
    init_kernel<<<(NB * NU + 255) / 256, 256>>>(a0, c0);

    // encoder: per-group GEMM [128 x 512 x 174] + leaky, then LN
    {
        dim3 ge(NEF / 64, NB / 64, NG);
        gemm64_kernel<false, 1><<<ge, 256>>>(
            features, NG * NGI, (size_t)NGI,
            enc_W, NEF, (size_t)NGI * NEF,
            enc_b, (size_t)NEF,
            p_feat, NG * NEF, (size_t)NEF,
            NB, NEF, NGI);
        ln_rows_kernel<<<NB * NG, 128>>>(p_feat, enc_ln_g, enc_ln_b);
    }
    // f1 = relu(feat @ attn_W1 + b1): [46080 x 32 x 512]
    {
        dim3 gf1(1, (NB * NG) / 64, 1);
        gemm64_kernel<false, 2><<<gf1, 256>>>(
            p_feat, NEF, 0, attn_W1, NAU, 0, attn_b1, 0,
            p_f1, NAU, 0, NB * NG, NAU, NEF);
    }

    for (int t = 0; t < NT; t++) {
        const float* a_in = p_aseq + (size_t)t * NB * NU;
        float* a_next     = p_aseq + (size_t)(t + 1) * NB * NU;
        attn_kernel<<<NB, 512>>>(p_f1, p_feat, a_in, attn_W2, attn_b2, attn_V, attn_bV,
                                 emb, text, p_x, attn_out, t);
        {   // gates split-K: 4 partials of [128 x 2048 x 384]
            dim3 gg(N4U / 64, NB / 64, NSK);
            gemm64_kernel<true, 0><<<gg, 256>>>(
                p_x, NKX, (size_t)NKSP,
                p_W, NKX, (size_t)NKSP,
                nullptr, 0,
                p_gp, N4U, (size_t)NB * N4U,
                NB, N4U, NKSP);
        }
        lstm_kernel<<<NB, 512>>>(p_gp, a_next, p_c, ln_g, ln_b, p_bs);
    }

    // ---- deferred decoder over all T*B rows (row r = t*NB + b) ----
    {   // d1 = leaky(aseq[1..T] @ dec_W1 + b1): [2560 x 256 x 512]
        dim3 gd1(256 / 64, (NT * NB) / 64, 1);
        gemm64_kernel<false, 1><<<gd1, 256>>>(
            p_aseq + (size_t)NB * NU, NU, 0, dec_W1, 256, 0, dec_b1, 0,
            p_d1, 256, 0, NT * NB, 256, NU);
    }
    {   // logits = d1 @ dec_W2 + b2: [2560 x 5000 x 256]
        dim3 gd2((NVOC + 63) / 64, (NT * NB) / 64, 1);
        gemm64_kernel<false, 0><<<gd2, 256>>>(
            p_d1, 256, 0, dec_W2, NVOC, 0, dec_b2, 0,
            p_lg, NVOC, 0, NT * NB, NVOC, 256);
    }
    vsm_kernel<<<NT * NB, 512>>>(p_lg, out);
}